// round 2
// baseline (speedup 1.0000x reference)
#include <cuda_runtime.h>
#include <cuda_bf16.h>

#define BB   32
#define TT   96
#define HID  256
#define CE   400
#define VV   256
#define HH_  16
#define WW_  64
#define AA   256
#define HW   1024

// ---------------- device scratch ----------------
__device__ __align__(16) float g_x0[BB*TT*HID];
__device__ __align__(16) float g_x1[BB*TT*HID];
__device__ __align__(16) float g_wT1[3*256*512];
__device__ __align__(16) float g_wT2[3*256*512];
__device__ __align__(16) float g_wT3[3*256*512];
__device__ __align__(16) float g_WhT[HID*AA];
__device__ __align__(16) float g_fcWT[(HID+CE)*VV];
__device__ __align__(16) float g_Wcpad[AA*28];
__device__ __align__(16) float g_EP[BB*AA*HW];     // (b, a, hw), includes b_enc
__device__ __align__(16) float g_QB[BB*TT*AA];     // q + b_h + b_cov
__device__ __align__(16) float g_cov[BB*HW];
__device__ __align__(16) float g_e[BB*HW];
__device__ __align__(16) float g_ctxall[BB*TT*CE];

__device__ __forceinline__ float sigmoid_fast(float x) {
    return __fdividef(1.f, 1.f + __expf(-x));
}

// ---------------- prep: embedding, weight transposes, zero cov ----------------
__global__ void __launch_bounds__(256) prep_kernel(const int* __restrict__ tgt,
                            const float* __restrict__ embed,
                            const float* __restrict__ w1,
                            const float* __restrict__ w2,
                            const float* __restrict__ w3,
                            const float* __restrict__ W_h,
                            const float* __restrict__ fc_W,
                            const float* __restrict__ W_cov) {
    int idx = blockIdx.x * 256 + threadIdx.x;
    if (idx < BB*TT*HID) {
        int bt = idx >> 8;
        g_x0[idx] = embed[tgt[bt]*HID + (idx & 255)];
    }
    if (idx < 512*256*3) {
        int o = idx / 768, rem = idx % 768, ic = rem / 3, k = rem % 3;
        int d = (k*256 + ic)*512 + o;
        g_wT1[d] = w1[idx];
        g_wT2[d] = w2[idx];
        g_wT3[d] = w3[idx];
    }
    if (idx < AA*HID) {
        int a = idx >> 8, h = idx & 255;
        g_WhT[h*AA + a] = W_h[idx];
    }
    if (idx < VV*(HID+CE)) {
        int v = idx / (HID+CE), j = idx % (HID+CE);
        g_fcWT[j*VV + v] = fc_W[idx];
    }
    if (idx < AA*28) {
        int a = idx / 28, i = idx % 28;
        g_Wcpad[idx] = (i < 25) ? W_cov[a*25 + i] : 0.f;
    }
    if (idx < BB*HW) g_cov[idx] = 0.f;
}

// ---------------- causal GLU layer ----------------
// y[b,t,o] = bias[o] + sum_{k,ic} x[b,t-2+k,ic] * wT[k][ic][o]; out = a*sigmoid(g)
__global__ void __launch_bounds__(256) glu_kernel(int src_sel, int layer,
                                                  const float* __restrict__ bias) {
    const float* xin  = src_sel ? g_x1 : g_x0;
    float*       xout = src_sel ? g_x0 : g_x1;
    const float* wT = (layer == 0) ? g_wT1 : (layer == 1) ? g_wT2 : g_wT3;

    int b  = blockIdx.x / 3;
    int t0 = (blockIdx.x % 3) * 32;
    int h0 = blockIdx.y * 64;
    __shared__ float As[34][17];
    __shared__ float Wa[3][16][64];
    __shared__ float Wg[3][16][64];
    int tid = threadIdx.x;
    int tr = (tid & 15) * 2;
    int tc = (tid >> 4) * 4;
    float aa[2][4], gg[2][4];
#pragma unroll
    for (int r = 0; r < 2; r++)
#pragma unroll
        for (int c = 0; c < 4; c++) { aa[r][c] = 0.f; gg[r][c] = 0.f; }

    for (int ic0 = 0; ic0 < 256; ic0 += 16) {
        __syncthreads();
        for (int idx = tid; idx < 34*16; idx += 256) {
            int r = idx >> 4, c = idx & 15;
            int tg = t0 - 2 + r;
            As[r][c] = (tg >= 0) ? xin[(b*TT + tg)*HID + ic0 + c] : 0.f;
        }
        for (int idx = tid; idx < 3072; idx += 256) {
            int k = idx >> 10, rem = idx & 1023, i = rem >> 6, j = rem & 63;
            const float* base = wT + (k*256 + ic0 + i)*512 + h0 + j;
            Wa[k][i][j] = base[0];
            Wg[k][i][j] = base[256];
        }
        __syncthreads();
#pragma unroll
        for (int k = 0; k < 3; k++) {
#pragma unroll
            for (int i = 0; i < 16; i++) {
                float x0 = As[tr + k][i];
                float x1 = As[tr + 1 + k][i];
#pragma unroll
                for (int c = 0; c < 4; c++) {
                    float wa = Wa[k][i][tc + c];
                    float wg = Wg[k][i][tc + c];
                    aa[0][c] = fmaf(x0, wa, aa[0][c]);
                    aa[1][c] = fmaf(x1, wa, aa[1][c]);
                    gg[0][c] = fmaf(x0, wg, gg[0][c]);
                    gg[1][c] = fmaf(x1, wg, gg[1][c]);
                }
            }
        }
    }
#pragma unroll
    for (int r = 0; r < 2; r++)
#pragma unroll
        for (int c = 0; c < 4; c++) {
            int t = t0 + tr + r, h = h0 + tc + c;
            float av = aa[r][c] + bias[h];
            float gv = gg[r][c] + bias[256 + h];
            xout[(b*TT + t)*HID + h] = av * sigmoid_fast(gv);
        }
}

// ---------------- enc_proj: EP[b,a,hw] = W_enc @ enc_feat + b_enc ----------------
__global__ void __launch_bounds__(256) encproj_kernel(const float* __restrict__ enc_feat,
                                                      const float* __restrict__ W_enc,
                                                      const float* __restrict__ b_enc) {
    int b = blockIdx.x, a0 = blockIdx.y*64, p0 = blockIdx.z*64;
    __shared__ float Ws[16][66];   // [c][a]
    __shared__ float Fs[16][64];   // [c][p]
    int tid = threadIdx.x;
    int ta = (tid & 15)*4, tp = (tid >> 4)*4;
    float acc[4][4];
#pragma unroll
    for (int r = 0; r < 4; r++)
#pragma unroll
        for (int c = 0; c < 4; c++) acc[r][c] = 0.f;

    for (int c0 = 0; c0 < CE; c0 += 16) {
        __syncthreads();
        for (int idx = tid; idx < 1024; idx += 256) {
            int j = idx & 15, i = idx >> 4;
            Ws[j][i] = W_enc[(a0 + i)*CE + c0 + j];
        }
        for (int idx = tid; idx < 1024; idx += 256) {
            int i = idx & 63, j = idx >> 6;
            Fs[j][i] = enc_feat[((size_t)b*CE + c0 + j)*HW + p0 + i];
        }
        __syncthreads();
#pragma unroll
        for (int j = 0; j < 16; j++) {
            float av[4], pv[4];
#pragma unroll
            for (int r = 0; r < 4; r++) av[r] = Ws[j][ta + r];
#pragma unroll
            for (int c = 0; c < 4; c++) pv[c] = Fs[j][tp + c];
#pragma unroll
            for (int r = 0; r < 4; r++)
#pragma unroll
                for (int c = 0; c < 4; c++)
                    acc[r][c] = fmaf(av[r], pv[c], acc[r][c]);
        }
    }
#pragma unroll
    for (int r = 0; r < 4; r++) {
        int a = a0 + ta + r;
        float be = b_enc[a];
#pragma unroll
        for (int c = 0; c < 4; c++)
            g_EP[((size_t)b*AA + a)*HW + p0 + tp + c] = acc[r][c] + be;
    }
}

// ---------------- q precompute: QB[bt,a] = hidd @ WhT + b_h + b_cov ----------------
__global__ void __launch_bounds__(256) qgemm_kernel(const float* __restrict__ b_h,
                                                    const float* __restrict__ b_cov) {
    int m0 = blockIdx.x * 64;
    int n0 = blockIdx.y * 64;
    __shared__ float Hs[16][66];
    __shared__ float Ws[16][64];
    int tid = threadIdx.x;
    int tm = (tid & 15)*4, tn = (tid >> 4)*4;
    float acc[4][4];
#pragma unroll
    for (int r = 0; r < 4; r++)
#pragma unroll
        for (int c = 0; c < 4; c++) acc[r][c] = 0.f;

    for (int k0 = 0; k0 < HID; k0 += 16) {
        __syncthreads();
        for (int idx = tid; idx < 1024; idx += 256) {
            int kk = idx & 15, m = idx >> 4;
            Hs[kk][m] = g_x1[(m0 + m)*HID + k0 + kk];
        }
        for (int idx = tid; idx < 1024; idx += 256) {
            int i = idx & 63, kk = idx >> 6;
            Ws[kk][i] = g_WhT[(k0 + kk)*AA + n0 + i];
        }
        __syncthreads();
#pragma unroll
        for (int kk = 0; kk < 16; kk++) {
            float hv[4], wv[4];
#pragma unroll
            for (int r = 0; r < 4; r++) hv[r] = Hs[kk][tm + r];
#pragma unroll
            for (int c = 0; c < 4; c++) wv[c] = Ws[kk][tn + c];
#pragma unroll
            for (int r = 0; r < 4; r++)
#pragma unroll
                for (int c = 0; c < 4; c++)
                    acc[r][c] = fmaf(hv[r], wv[c], acc[r][c]);
        }
    }
#pragma unroll
    for (int r = 0; r < 4; r++)
#pragma unroll
        for (int c = 0; c < 4; c++) {
            int n = n0 + tn + c;
            g_QB[(m0 + tm + r)*AA + n] = acc[r][c] + b_h[n] + b_cov[n];
        }
}

// ---------------- per-step energy: e[b,hw] = sum_a v[a] * tanh(EP + q + conv(cov)) ----------------
__global__ void __launch_bounds__(128) energy_kernel(const float* __restrict__ v_attn, int t) {
    int b  = blockIdx.x;
    int r0 = blockIdx.y * 2;   // 2 rows of 64 pixels
    __shared__ float sCov[6][68];
    __shared__ float sW[256*28];
    __shared__ float sQ[256];
    __shared__ float sV[256];
    int tid = threadIdx.x;

    for (int idx = tid; idx < 6*68; idx += 128) {
        int rr = idx / 68, cc = idx % 68;
        int h = r0 - 2 + rr, w = cc - 2;
        sCov[rr][cc] = (h >= 0 && h < HH_ && w >= 0 && w < WW_)
                       ? g_cov[b*HW + h*WW_ + w] : 0.f;
    }
    for (int idx = tid; idx < 1792; idx += 128)
        ((float4*)sW)[idx] = ((const float4*)g_Wcpad)[idx];
    sQ[tid]       = g_QB[(b*TT + t)*AA + tid];
    sQ[tid + 128] = g_QB[(b*TT + t)*AA + tid + 128];
    sV[tid]       = v_attn[tid];
    sV[tid + 128] = v_attn[tid + 128];
    __syncthreads();

    int lr = tid >> 6;       // 0..1
    int w  = tid & 63;
    int pix = (r0 + lr)*WW_ + w;

    float p[25];
#pragma unroll
    for (int dy = 0; dy < 5; dy++)
#pragma unroll
        for (int dx = 0; dx < 5; dx++)
            p[dy*5 + dx] = sCov[lr + dy][w + dx];

    const float* epp = g_EP + (size_t)b * (AA*HW) + pix;
    float e_acc = 0.f;
    float ep4[4];
#pragma unroll
    for (int u = 0; u < 4; u++) ep4[u] = epp[u*HW];

    for (int a0 = 0; a0 < 256; a0 += 4) {
        float nxt[4];
        if (a0 < 252) {
#pragma unroll
            for (int u = 0; u < 4; u++) nxt[u] = epp[(a0 + 4 + u)*HW];
        } else {
#pragma unroll
            for (int u = 0; u < 4; u++) nxt[u] = 0.f;
        }
#pragma unroll
        for (int u = 0; u < 4; u++) {
            int a = a0 + u;
            const float4* wc = (const float4*)(sW + a*28);
            float4 w0 = wc[0], w1 = wc[1], w2 = wc[2], w3 = wc[3];
            float4 w4 = wc[4], w5 = wc[5], w6 = wc[6];
            float s0 = p[0]*w0.x, s1 = p[1]*w0.y, s2 = p[2]*w0.z, s3 = p[3]*w0.w;
            s0 = fmaf(p[4],  w1.x, s0); s1 = fmaf(p[5],  w1.y, s1);
            s2 = fmaf(p[6],  w1.z, s2); s3 = fmaf(p[7],  w1.w, s3);
            s0 = fmaf(p[8],  w2.x, s0); s1 = fmaf(p[9],  w2.y, s1);
            s2 = fmaf(p[10], w2.z, s2); s3 = fmaf(p[11], w2.w, s3);
            s0 = fmaf(p[12], w3.x, s0); s1 = fmaf(p[13], w3.y, s1);
            s2 = fmaf(p[14], w3.z, s2); s3 = fmaf(p[15], w3.w, s3);
            s0 = fmaf(p[16], w4.x, s0); s1 = fmaf(p[17], w4.y, s1);
            s2 = fmaf(p[18], w4.z, s2); s3 = fmaf(p[19], w4.w, s3);
            s0 = fmaf(p[20], w5.x, s0); s1 = fmaf(p[21], w5.y, s1);
            s2 = fmaf(p[22], w5.z, s2); s3 = fmaf(p[23], w5.w, s3);
            s0 = fmaf(p[24], w6.x, s0);
            float s = ((s0 + s1) + (s2 + s3)) + ep4[u] + sQ[a];
            // tanh(s) = 1 - 2/(exp(2s)+1), accurate to ~1e-6
            float ex = __expf(2.f * s);
            float th = 1.f - __fdividef(2.f, ex + 1.f);
            e_acc = fmaf(sV[a], th, e_acc);
        }
#pragma unroll
        for (int u = 0; u < 4; u++) ep4[u] = nxt[u];
    }
    g_e[b*HW + pix] = e_acc;
}

// ---------------- per-step softmax + cov update + ctx ----------------
__global__ void __launch_bounds__(256) attnctx_kernel(const float* __restrict__ enc_feat, int t) {
    int b  = blockIdx.x;
    int cb = blockIdx.y;   // 0..7, 50 channels each
    __shared__ float sA[1024];
    __shared__ float redm[8];
    __shared__ float reds[8];
    int tid = threadIdx.x, lane = tid & 31, warp = tid >> 5;

    float4 ev = ((const float4*)(g_e + b*HW))[tid];
    float m = fmaxf(fmaxf(ev.x, ev.y), fmaxf(ev.z, ev.w));
#pragma unroll
    for (int o = 16; o; o >>= 1) m = fmaxf(m, __shfl_xor_sync(~0u, m, o));
    if (lane == 0) redm[warp] = m;
    __syncthreads();
    m = redm[0];
#pragma unroll
    for (int i = 1; i < 8; i++) m = fmaxf(m, redm[i]);

    float4 exv;
    exv.x = __expf(ev.x - m); exv.y = __expf(ev.y - m);
    exv.z = __expf(ev.z - m); exv.w = __expf(ev.w - m);
    float s = exv.x + exv.y + exv.z + exv.w;
#pragma unroll
    for (int o = 16; o; o >>= 1) s += __shfl_xor_sync(~0u, s, o);
    if (lane == 0) reds[warp] = s;
    __syncthreads();
    s = reds[0];
#pragma unroll
    for (int i = 1; i < 8; i++) s += reds[i];
    float inv = __fdividef(1.f, s);

    float4 al;
    al.x = exv.x*inv; al.y = exv.y*inv; al.z = exv.z*inv; al.w = exv.w*inv;
    ((float4*)sA)[tid] = al;

    if (cb == 0) {
        float4* cv = (float4*)(g_cov + b*HW);
        float4 c = cv[tid];
        c.x += al.x; c.y += al.y; c.z += al.z; c.w += al.w;
        cv[tid] = c;
    }
    __syncthreads();

    for (int ci = warp; ci < 50; ci += 8) {
        int c = cb*50 + ci;
        const float4* f  = (const float4*)(enc_feat + ((size_t)b*CE + c)*HW);
        const float4* a4 = (const float4*)sA;
        float acc = 0.f;
        for (int i = lane; i < 256; i += 32) {
            float4 fv = f[i], av = a4[i];
            acc = fmaf(fv.x, av.x, acc);
            acc = fmaf(fv.y, av.y, acc);
            acc = fmaf(fv.z, av.z, acc);
            acc = fmaf(fv.w, av.w, acc);
        }
#pragma unroll
        for (int o = 16; o; o >>= 1) acc += __shfl_xor_sync(~0u, acc, o);
        if (lane == 0) g_ctxall[((b*TT) + t)*CE + c] = acc;
    }
}

// ---------------- final fc: logits = [hidd, ctx] @ fcWT + fc_b ----------------
__global__ void __launch_bounds__(256) fc_kernel(const float* __restrict__ fc_b,
                                                 float* __restrict__ out) {
    int m0 = blockIdx.x * 64;
    int n0 = blockIdx.y * 64;
    __shared__ float Is[16][66];
    __shared__ float Ws[16][64];
    int tid = threadIdx.x;
    int tm = (tid & 15)*4, tn = (tid >> 4)*4;
    float acc[4][4];
#pragma unroll
    for (int r = 0; r < 4; r++)
#pragma unroll
        for (int c = 0; c < 4; c++) acc[r][c] = 0.f;

    for (int k0 = 0; k0 < HID + CE; k0 += 16) {
        __syncthreads();
        const float* src; int stride, off;
        if (k0 < HID) { src = g_x1;     stride = HID; off = k0; }
        else          { src = g_ctxall; stride = CE;  off = k0 - HID; }
        for (int idx = tid; idx < 1024; idx += 256) {
            int kk = idx & 15, mm = idx >> 4;
            Is[kk][mm] = src[(m0 + mm)*stride + off + kk];
        }
        for (int idx = tid; idx < 1024; idx += 256) {
            int i = idx & 63, kk = idx >> 6;
            Ws[kk][i] = g_fcWT[(k0 + kk)*VV + n0 + i];
        }
        __syncthreads();
#pragma unroll
        for (int kk = 0; kk < 16; kk++) {
            float iv[4], wv[4];
#pragma unroll
            for (int r = 0; r < 4; r++) iv[r] = Is[kk][tm + r];
#pragma unroll
            for (int c = 0; c < 4; c++) wv[c] = Ws[kk][tn + c];
#pragma unroll
            for (int r = 0; r < 4; r++)
#pragma unroll
                for (int c = 0; c < 4; c++)
                    acc[r][c] = fmaf(iv[r], wv[c], acc[r][c]);
        }
    }
#pragma unroll
    for (int r = 0; r < 4; r++)
#pragma unroll
        for (int c = 0; c < 4; c++) {
            int n = n0 + tn + c;
            out[(m0 + tm + r)*VV + n] = acc[r][c] + fc_b[n];
        }
}

// ---------------- launch ----------------
extern "C" void kernel_launch(void* const* d_in, const int* in_sizes, int n_in,
                              void* d_out, int out_size) {
    const float* enc_feat = (const float*)d_in[0];
    const int*   tgt      = (const int*)  d_in[1];
    const float* embed    = (const float*)d_in[2];
    const float* w1       = (const float*)d_in[3];
    const float* b1       = (const float*)d_in[4];
    const float* w2       = (const float*)d_in[5];
    const float* b2       = (const float*)d_in[6];
    const float* w3       = (const float*)d_in[7];
    const float* b3       = (const float*)d_in[8];
    const float* W_enc    = (const float*)d_in[9];
    const float* b_enc    = (const float*)d_in[10];
    const float* W_h      = (const float*)d_in[11];
    const float* b_h      = (const float*)d_in[12];
    const float* W_cov    = (const float*)d_in[13];
    const float* b_cov    = (const float*)d_in[14];
    const float* v_attn   = (const float*)d_in[15];
    const float* fc_W     = (const float*)d_in[16];
    const float* fc_b     = (const float*)d_in[17];
    float* out = (float*)d_out;

    prep_kernel<<<3072, 256>>>(tgt, embed, w1, w2, w3, W_h, fc_W, W_cov);

    dim3 gglu(BB*3, 4);
    glu_kernel<<<gglu, 256>>>(0, 0, b1);   // g_x0 -> g_x1
    glu_kernel<<<gglu, 256>>>(1, 1, b2);   // g_x1 -> g_x0
    glu_kernel<<<gglu, 256>>>(0, 2, b3);   // g_x0 -> g_x1 (= hidd)

    encproj_kernel<<<dim3(BB, 4, 16), 256>>>(enc_feat, W_enc, b_enc);
    qgemm_kernel<<<dim3(48, 4), 256>>>(b_h, b_cov);

    for (int t = 0; t < TT; t++) {
        energy_kernel<<<dim3(BB, 8), 128>>>(v_attn, t);
        attnctx_kernel<<<dim3(BB, 8), 256>>>(enc_feat, t);
    }

    fc_kernel<<<dim3(48, 4), 256>>>(fc_b, out);
}

// round 4
// speedup vs baseline: 1.1732x; 1.1732x over previous
#include <cuda_runtime.h>
#include <cuda_bf16.h>

#define BB   32
#define TT   96
#define HID  256
#define CE   400
#define VV   256
#define HH_  16
#define WW_  64
#define AA   256
#define HW   1024
#define NZ   8          // a-chunks
#define ACH  32         // a per chunk

// ---------------- device scratch ----------------
__device__ __align__(16) float g_x0[BB*TT*HID];
__device__ __align__(16) float g_x1[BB*TT*HID];
__device__ __align__(16) float g_wT1[3*256*512];
__device__ __align__(16) float g_wT2[3*256*512];
__device__ __align__(16) float g_wT3[3*256*512];
__device__ __align__(16) float g_WhT[HID*AA];
__device__ __align__(16) float g_fcWT[(HID+CE)*VV];
__device__ __align__(16) float2 g_Wc2[AA*26];      // dup-packed (w,w), 26th = pad 0
__device__ __align__(16) float g_EP[BB*AA*HW];     // (b, a, hw), includes b_enc
__device__ __align__(16) float g_QB[BB*TT*AA];     // q + b_h + b_cov
__device__ __align__(16) float g_cov[BB*HW];
__device__ __align__(16) float g_epart[NZ*BB*HW];  // partial e per a-chunk
__device__ __align__(16) float g_ctxall[BB*TT*CE];

__device__ __forceinline__ float sigmoid_fast(float x) {
    return __fdividef(1.f, 1.f + __expf(-x));
}

// ---- packed f32x2 helpers (sm_103a) ----
typedef unsigned long long u64;
__device__ __forceinline__ u64 pk2(float lo, float hi) {
    u64 d;
    asm("mov.b64 %0, {%1, %2};" : "=l"(d) : "r"(__float_as_uint(lo)), "r"(__float_as_uint(hi)));
    return d;
}
__device__ __forceinline__ void upk2(u64 v, float& lo, float& hi) {
    unsigned int a, b;
    asm("mov.b64 {%0, %1}, %2;" : "=r"(a), "=r"(b) : "l"(v));
    lo = __uint_as_float(a); hi = __uint_as_float(b);
}
__device__ __forceinline__ u64 ffma2(u64 a, u64 b, u64 c) {
    u64 d;
    asm("fma.rn.f32x2 %0, %1, %2, %3;" : "=l"(d) : "l"(a), "l"(b), "l"(c));
    return d;
}
__device__ __forceinline__ u64 fadd2(u64 a, u64 b) {
    u64 d;
    asm("add.rn.f32x2 %0, %1, %2;" : "=l"(d) : "l"(a), "l"(b));
    return d;
}
__device__ __forceinline__ float tanh_acc(float x) {
    float ex = __expf(x + x);
    return 1.f - __fdividef(2.f, ex + 1.f);
}

// ---------------- prep: embedding, weight transposes, zero cov ----------------
__global__ void __launch_bounds__(256) prep_kernel(const int* __restrict__ tgt,
                            const float* __restrict__ embed,
                            const float* __restrict__ w1,
                            const float* __restrict__ w2,
                            const float* __restrict__ w3,
                            const float* __restrict__ W_h,
                            const float* __restrict__ fc_W,
                            const float* __restrict__ W_cov) {
    int idx = blockIdx.x * 256 + threadIdx.x;
    if (idx < BB*TT*HID) {
        int bt = idx >> 8;
        g_x0[idx] = embed[tgt[bt]*HID + (idx & 255)];
    }
    if (idx < 512*256*3) {
        int o = idx / 768, rem = idx % 768, ic = rem / 3, k = rem % 3;
        int d = (k*256 + ic)*512 + o;
        g_wT1[d] = w1[idx];
        g_wT2[d] = w2[idx];
        g_wT3[d] = w3[idx];
    }
    if (idx < AA*HID) {
        int a = idx >> 8, h = idx & 255;
        g_WhT[h*AA + a] = W_h[idx];
    }
    if (idx < VV*(HID+CE)) {
        int v = idx / (HID+CE), j = idx % (HID+CE);
        g_fcWT[j*VV + v] = fc_W[idx];
    }
    if (idx < AA*26) {
        int a = idx / 26, k = idx % 26;
        float w = (k < 25) ? W_cov[a*25 + k] : 0.f;
        g_Wc2[idx] = make_float2(w, w);
    }
    if (idx < BB*HW) g_cov[idx] = 0.f;
}

// ---------------- causal GLU layer (32t x 32h tiles) ----------------
__global__ void __launch_bounds__(256) glu_kernel(int src_sel, int layer,
                                                  const float* __restrict__ bias) {
    const float* xin  = src_sel ? g_x1 : g_x0;
    float*       xout = src_sel ? g_x0 : g_x1;
    const float* wT = (layer == 0) ? g_wT1 : (layer == 1) ? g_wT2 : g_wT3;

    int b  = blockIdx.x / 3;
    int t0 = (blockIdx.x % 3) * 32;
    int h0 = blockIdx.y * 32;
    __shared__ float As[34][17];
    __shared__ float Wa[3][16][32];
    __shared__ float Wg[3][16][32];
    int tid = threadIdx.x;
    int tr = (tid & 15) * 2;
    int tc = (tid >> 4) * 2;
    float aa[2][2], gg[2][2];
#pragma unroll
    for (int r = 0; r < 2; r++)
#pragma unroll
        for (int c = 0; c < 2; c++) { aa[r][c] = 0.f; gg[r][c] = 0.f; }

    for (int ic0 = 0; ic0 < 256; ic0 += 16) {
        __syncthreads();
        for (int idx = tid; idx < 34*16; idx += 256) {
            int r = idx >> 4, c = idx & 15;
            int tg = t0 - 2 + r;
            As[r][c] = (tg >= 0) ? xin[(b*TT + tg)*HID + ic0 + c] : 0.f;
        }
        for (int idx = tid; idx < 1536; idx += 256) {
            int k = idx >> 9, rem = idx & 511, i = rem >> 5, j = rem & 31;
            const float* base = wT + (k*256 + ic0 + i)*512 + h0 + j;
            Wa[k][i][j] = base[0];
            Wg[k][i][j] = base[256];
        }
        __syncthreads();
#pragma unroll
        for (int k = 0; k < 3; k++) {
#pragma unroll
            for (int i = 0; i < 16; i++) {
                float x0 = As[tr + k][i];
                float x1 = As[tr + 1 + k][i];
                float wa0 = Wa[k][i][tc],   wa1 = Wa[k][i][tc+1];
                float wg0 = Wg[k][i][tc],   wg1 = Wg[k][i][tc+1];
                aa[0][0] = fmaf(x0, wa0, aa[0][0]);
                aa[0][1] = fmaf(x0, wa1, aa[0][1]);
                aa[1][0] = fmaf(x1, wa0, aa[1][0]);
                aa[1][1] = fmaf(x1, wa1, aa[1][1]);
                gg[0][0] = fmaf(x0, wg0, gg[0][0]);
                gg[0][1] = fmaf(x0, wg1, gg[0][1]);
                gg[1][0] = fmaf(x1, wg0, gg[1][0]);
                gg[1][1] = fmaf(x1, wg1, gg[1][1]);
            }
        }
    }
#pragma unroll
    for (int r = 0; r < 2; r++)
#pragma unroll
        for (int c = 0; c < 2; c++) {
            int t = t0 + tr + r, h = h0 + tc + c;
            float av = aa[r][c] + bias[h];
            float gv = gg[r][c] + bias[256 + h];
            xout[(b*TT + t)*HID + h] = av * sigmoid_fast(gv);
        }
}

// ---------------- enc_proj: EP[b,a,hw] = W_enc @ enc_feat + b_enc ----------------
__global__ void __launch_bounds__(256) encproj_kernel(const float* __restrict__ enc_feat,
                                                      const float* __restrict__ W_enc,
                                                      const float* __restrict__ b_enc) {
    int b = blockIdx.x, a0 = blockIdx.y*64, p0 = blockIdx.z*64;
    __shared__ float Ws[16][66];
    __shared__ float Fs[16][64];
    int tid = threadIdx.x;
    int ta = (tid & 15)*4, tp = (tid >> 4)*4;
    float acc[4][4];
#pragma unroll
    for (int r = 0; r < 4; r++)
#pragma unroll
        for (int c = 0; c < 4; c++) acc[r][c] = 0.f;

    for (int c0 = 0; c0 < CE; c0 += 16) {
        __syncthreads();
        for (int idx = tid; idx < 1024; idx += 256) {
            int j = idx & 15, i = idx >> 4;
            Ws[j][i] = W_enc[(a0 + i)*CE + c0 + j];
        }
        for (int idx = tid; idx < 1024; idx += 256) {
            int i = idx & 63, j = idx >> 6;
            Fs[j][i] = enc_feat[((size_t)b*CE + c0 + j)*HW + p0 + i];
        }
        __syncthreads();
#pragma unroll
        for (int j = 0; j < 16; j++) {
            float av[4], pv[4];
#pragma unroll
            for (int r = 0; r < 4; r++) av[r] = Ws[j][ta + r];
#pragma unroll
            for (int c = 0; c < 4; c++) pv[c] = Fs[j][tp + c];
#pragma unroll
            for (int r = 0; r < 4; r++)
#pragma unroll
                for (int c = 0; c < 4; c++)
                    acc[r][c] = fmaf(av[r], pv[c], acc[r][c]);
        }
    }
#pragma unroll
    for (int r = 0; r < 4; r++) {
        int a = a0 + ta + r;
        float be = b_enc[a];
#pragma unroll
        for (int c = 0; c < 4; c++)
            g_EP[((size_t)b*AA + a)*HW + p0 + tp + c] = acc[r][c] + be;
    }
}

// ---------------- q precompute ----------------
__global__ void __launch_bounds__(256) qgemm_kernel(const float* __restrict__ b_h,
                                                    const float* __restrict__ b_cov) {
    int m0 = blockIdx.x * 64;
    int n0 = blockIdx.y * 64;
    __shared__ float Hs[16][66];
    __shared__ float Ws[16][64];
    int tid = threadIdx.x;
    int tm = (tid & 15)*4, tn = (tid >> 4)*4;
    float acc[4][4];
#pragma unroll
    for (int r = 0; r < 4; r++)
#pragma unroll
        for (int c = 0; c < 4; c++) acc[r][c] = 0.f;

    for (int k0 = 0; k0 < HID; k0 += 16) {
        __syncthreads();
        for (int idx = tid; idx < 1024; idx += 256) {
            int kk = idx & 15, m = idx >> 4;
            Hs[kk][m] = g_x1[(m0 + m)*HID + k0 + kk];
        }
        for (int idx = tid; idx < 1024; idx += 256) {
            int i = idx & 63, kk = idx >> 6;
            Ws[kk][i] = g_WhT[(k0 + kk)*AA + n0 + i];
        }
        __syncthreads();
#pragma unroll
        for (int kk = 0; kk < 16; kk++) {
            float hv[4], wv[4];
#pragma unroll
            for (int r = 0; r < 4; r++) hv[r] = Hs[kk][tm + r];
#pragma unroll
            for (int c = 0; c < 4; c++) wv[c] = Ws[kk][tn + c];
#pragma unroll
            for (int r = 0; r < 4; r++)
#pragma unroll
                for (int c = 0; c < 4; c++)
                    acc[r][c] = fmaf(hv[r], wv[c], acc[r][c]);
        }
    }
#pragma unroll
    for (int r = 0; r < 4; r++)
#pragma unroll
        for (int c = 0; c < 4; c++) {
            int n = n0 + tn + c;
            g_QB[(m0 + tm + r)*AA + n] = acc[r][c] + b_h[n] + b_cov[n];
        }
}

// ---------------- per-step energy (f32x2-packed, a-chunked) ----------------
// block: (b, strip 0..1 of 8 pixel rows, a-chunk 0..7). 128 threads, 4 px each.
__global__ void __launch_bounds__(128) energy_kernel(const float* __restrict__ v_attn, int t) {
    int b     = blockIdx.x;
    int strip = blockIdx.y;
    int zc    = blockIdx.z;
    int a0    = zc * ACH;
    __shared__ float sCov[12][68];
    __shared__ __align__(16) float2 sW[ACH*26];
    __shared__ float2 sQ2[ACH];
    __shared__ float2 sV2[ACH];
    int tid = threadIdx.x;
    int r0 = strip * 8;

    for (int idx = tid; idx < 12*68; idx += 128) {
        int rr = idx / 68, cc = idx % 68;
        int h = r0 - 2 + rr, w = cc - 2;
        sCov[rr][cc] = (h >= 0 && h < HH_ && (unsigned)w < WW_)
                       ? g_cov[b*HW + h*WW_ + w] : 0.f;
    }
    for (int idx = tid; idx < ACH*26; idx += 128)
        sW[idx] = g_Wc2[a0*26 + idx];
    if (tid < ACH) {
        float q = g_QB[(b*TT + t)*AA + a0 + tid];
        sQ2[tid] = make_float2(q, q);
        float v = v_attn[a0 + tid];
        sV2[tid] = make_float2(v, v);
    }
    __syncthreads();

    int row = tid >> 4;
    int c0  = (tid & 15) * 4;

    // pre-packed overlapping patch: pp[dy][dx] = (patch[dy][dx], patch[dy][dx+1])
    u64 pp[5][7];
#pragma unroll
    for (int dy = 0; dy < 5; dy++)
#pragma unroll
        for (int dx = 0; dx < 7; dx++)
            pp[dy][dx] = pk2(sCov[row + dy][c0 + dx], sCov[row + dy][c0 + dx + 1]);

    int pix = (r0 + row)*WW_ + c0;
    const ulonglong2* ep2 = (const ulonglong2*)(g_EP + ((size_t)b*AA + a0)*HW + pix);
    const ulonglong2* wb  = (const ulonglong2*)sW;

    u64 e0 = 0ull, e1 = 0ull;   // packed (0,0)
    ulonglong2 epv = ep2[0];

#pragma unroll 1
    for (int aa = 0; aa < ACH; aa++) {
        ulonglong2 epn = epv;
        if (aa < ACH - 1) epn = ep2[(aa + 1) * (HW/4)];   // HW floats = HW/4 ulonglong2

        const ulonglong2* w2 = wb + aa*13;
        u64 a00 = 0ull, a01 = 0ull, a10 = 0ull, a11 = 0ull;
#pragma unroll
        for (int j = 0; j < 13; j++) {
            ulonglong2 w = w2[j];
            {   // tap k = 2j
                const int k = 2*j;
                if (k < 25) {
                    const int dy = k / 5, dx = k % 5;
                    a00 = ffma2(pp[dy][dx],     w.x, a00);
                    a10 = ffma2(pp[dy][dx + 2], w.x, a10);
                }
            }
            {   // tap k = 2j+1
                const int k = 2*j + 1;
                if (k < 25) {
                    const int dy = k / 5, dx = k % 5;
                    a01 = ffma2(pp[dy][dx],     w.y, a01);
                    a11 = ffma2(pp[dy][dx + 2], w.y, a11);
                }
            }
        }
        u64 q2 = *(const u64*)&sQ2[aa];
        u64 g0 = fadd2(fadd2(a00, a01), fadd2(epv.x, q2));
        u64 g1 = fadd2(fadd2(a10, a11), fadd2(epv.y, q2));
        float s0, s1, s2, s3;
        upk2(g0, s0, s1); upk2(g1, s2, s3);
        float t0 = tanh_acc(s0), t1 = tanh_acc(s1);
        float t2 = tanh_acc(s2), t3 = tanh_acc(s3);
        u64 v2 = *(const u64*)&sV2[aa];
        e0 = ffma2(pk2(t0, t1), v2, e0);
        e1 = ffma2(pk2(t2, t3), v2, e1);
        epv = epn;
    }
    float r0_, r1_, r2_, r3_;
    upk2(e0, r0_, r1_); upk2(e1, r2_, r3_);
    *(float4*)&g_epart[(zc*BB + b)*HW + pix] = make_float4(r0_, r1_, r2_, r3_);
}

// ---------------- per-step softmax + cov update + ctx ----------------
__global__ void __launch_bounds__(256) attnctx_kernel(const float* __restrict__ enc_feat, int t) {
    int b  = blockIdx.x;
    int cb = blockIdx.y;   // 0..15, 25 channels each
    __shared__ float sA[1024];
    __shared__ float redm[8];
    __shared__ float reds[8];
    int tid = threadIdx.x, lane = tid & 31, warp = tid >> 5;

    float4 ev = make_float4(0.f, 0.f, 0.f, 0.f);
#pragma unroll
    for (int z = 0; z < NZ; z++) {
        float4 p = ((const float4*)(g_epart + (z*BB + b)*HW))[tid];
        ev.x += p.x; ev.y += p.y; ev.z += p.z; ev.w += p.w;
    }
    float m = fmaxf(fmaxf(ev.x, ev.y), fmaxf(ev.z, ev.w));
#pragma unroll
    for (int o = 16; o; o >>= 1) m = fmaxf(m, __shfl_xor_sync(~0u, m, o));
    if (lane == 0) redm[warp] = m;
    __syncthreads();
    m = redm[0];
#pragma unroll
    for (int i = 1; i < 8; i++) m = fmaxf(m, redm[i]);

    float4 exv;
    exv.x = __expf(ev.x - m); exv.y = __expf(ev.y - m);
    exv.z = __expf(ev.z - m); exv.w = __expf(ev.w - m);
    float s = exv.x + exv.y + exv.z + exv.w;
#pragma unroll
    for (int o = 16; o; o >>= 1) s += __shfl_xor_sync(~0u, s, o);
    if (lane == 0) reds[warp] = s;
    __syncthreads();
    s = reds[0];
#pragma unroll
    for (int i = 1; i < 8; i++) s += reds[i];
    float inv = __fdividef(1.f, s);

    float4 al;
    al.x = exv.x*inv; al.y = exv.y*inv; al.z = exv.z*inv; al.w = exv.w*inv;
    ((float4*)sA)[tid] = al;

    if (cb == 0) {
        float4* cv = (float4*)(g_cov + b*HW);
        float4 c = cv[tid];
        c.x += al.x; c.y += al.y; c.z += al.z; c.w += al.w;
        cv[tid] = c;
    }
    __syncthreads();

    for (int ci = warp; ci < 25; ci += 8) {
        int c = cb*25 + ci;
        const float4* f  = (const float4*)(enc_feat + ((size_t)b*CE + c)*HW);
        const float4* a4 = (const float4*)sA;
        float acc = 0.f;
        for (int i = lane; i < 256; i += 32) {
            float4 fv = f[i], av = a4[i];
            acc = fmaf(fv.x, av.x, acc);
            acc = fmaf(fv.y, av.y, acc);
            acc = fmaf(fv.z, av.z, acc);
            acc = fmaf(fv.w, av.w, acc);
        }
#pragma unroll
        for (int o = 16; o; o >>= 1) acc += __shfl_xor_sync(~0u, acc, o);
        if (lane == 0) g_ctxall[((b*TT) + t)*CE + c] = acc;
    }
}

// ---------------- final fc ----------------
__global__ void __launch_bounds__(256) fc_kernel(const float* __restrict__ fc_b,
                                                 float* __restrict__ out) {
    int m0 = blockIdx.x * 64;
    int n0 = blockIdx.y * 64;
    __shared__ float Is[16][66];
    __shared__ float Ws[16][64];
    int tid = threadIdx.x;
    int tm = (tid & 15)*4, tn = (tid >> 4)*4;
    float acc[4][4];
#pragma unroll
    for (int r = 0; r < 4; r++)
#pragma unroll
        for (int c = 0; c < 4; c++) acc[r][c] = 0.f;

    for (int k0 = 0; k0 < HID + CE; k0 += 16) {
        __syncthreads();
        const float* src; int stride, off;
        if (k0 < HID) { src = g_x1;     stride = HID; off = k0; }
        else          { src = g_ctxall; stride = CE;  off = k0 - HID; }
        for (int idx = tid; idx < 1024; idx += 256) {
            int kk = idx & 15, mm = idx >> 4;
            Is[kk][mm] = src[(m0 + mm)*stride + off + kk];
        }
        for (int idx = tid; idx < 1024; idx += 256) {
            int i = idx & 63, kk = idx >> 6;
            Ws[kk][i] = g_fcWT[(k0 + kk)*VV + n0 + i];
        }
        __syncthreads();
#pragma unroll
        for (int kk = 0; kk < 16; kk++) {
            float iv[4], wv[4];
#pragma unroll
            for (int r = 0; r < 4; r++) iv[r] = Is[kk][tm + r];
#pragma unroll
            for (int c = 0; c < 4; c++) wv[c] = Ws[kk][tn + c];
#pragma unroll
            for (int r = 0; r < 4; r++)
#pragma unroll
                for (int c = 0; c < 4; c++)
                    acc[r][c] = fmaf(iv[r], wv[c], acc[r][c]);
        }
    }
#pragma unroll
    for (int r = 0; r < 4; r++)
#pragma unroll
        for (int c = 0; c < 4; c++) {
            int n = n0 + tn + c;
            out[(m0 + tm + r)*VV + n] = acc[r][c] + fc_b[n];
        }
}

// ---------------- launch ----------------
extern "C" void kernel_launch(void* const* d_in, const int* in_sizes, int n_in,
                              void* d_out, int out_size) {
    const float* enc_feat = (const float*)d_in[0];
    const int*   tgt      = (const int*)  d_in[1];
    const float* embed    = (const float*)d_in[2];
    const float* w1       = (const float*)d_in[3];
    const float* b1       = (const float*)d_in[4];
    const float* w2       = (const float*)d_in[5];
    const float* b2       = (const float*)d_in[6];
    const float* w3       = (const float*)d_in[7];
    const float* b3       = (const float*)d_in[8];
    const float* W_enc    = (const float*)d_in[9];
    const float* b_enc    = (const float*)d_in[10];
    const float* W_h      = (const float*)d_in[11];
    const float* b_h      = (const float*)d_in[12];
    const float* W_cov    = (const float*)d_in[13];
    const float* b_cov    = (const float*)d_in[14];
    const float* v_attn   = (const float*)d_in[15];
    const float* fc_W     = (const float*)d_in[16];
    const float* fc_b     = (const float*)d_in[17];
    float* out = (float*)d_out;

    prep_kernel<<<3072, 256>>>(tgt, embed, w1, w2, w3, W_h, fc_W, W_cov);

    dim3 gglu(BB*3, 8);
    glu_kernel<<<gglu, 256>>>(0, 0, b1);   // g_x0 -> g_x1
    glu_kernel<<<gglu, 256>>>(1, 1, b2);   // g_x1 -> g_x0
    glu_kernel<<<gglu, 256>>>(0, 2, b3);   // g_x0 -> g_x1 (= hidd)

    encproj_kernel<<<dim3(BB, 4, 16), 256>>>(enc_feat, W_enc, b_enc);
    qgemm_kernel<<<dim3(48, 4), 256>>>(b_h, b_cov);

    for (int t = 0; t < TT; t++) {
        energy_kernel<<<dim3(BB, 2, NZ), 128>>>(v_attn, t);
        attnctx_kernel<<<dim3(BB, 16), 256>>>(enc_feat, t);
    }

    fc_kernel<<<dim3(48, 4), 256>>>(fc_b, out);
}

// round 5
// speedup vs baseline: 1.4297x; 1.2187x over previous
#include <cuda_runtime.h>
#include <cuda_bf16.h>

#define BB   32
#define TT   96
#define HID  256
#define CE   400
#define VV   256
#define HH_  16
#define WW_  64
#define AA   256
#define HW   1024
#define NZ   8          // a-chunks
#define ACH  32         // a per chunk

// ---------------- device scratch ----------------
__device__ __align__(16) float g_x0[BB*TT*HID];
__device__ __align__(16) float g_x1[BB*TT*HID];
__device__ __align__(16) float g_wT1[3*256*512];
__device__ __align__(16) float g_wT2[3*256*512];
__device__ __align__(16) float g_wT3[3*256*512];
__device__ __align__(16) float g_WhT[HID*AA];
__device__ __align__(16) float g_fcWT[(HID+CE)*VV];
__device__ __align__(16) float2 g_Wc2[AA*26];      // dup-packed (w,w), 26th = pad 0
__device__ __align__(16) float g_EP[BB*AA*HW];     // (b, a, hw), includes b_enc
__device__ __align__(16) float g_QB[BB*TT*AA];     // q + b_h + b_cov
__device__ __align__(16) float g_cov[BB*HW];
__device__ __align__(16) float g_epart[NZ*BB*HW];  // partial e per a-chunk
__device__ __align__(16) float g_alpha[BB*TT*HW];  // all attention maps
__device__ __align__(16) float g_ctxall[BB*TT*CE];

__device__ __forceinline__ float sigmoid_fast(float x) {
    return __fdividef(1.f, 1.f + __expf(-x));
}

// ---- packed f32x2 helpers (sm_103a) ----
typedef unsigned long long u64;
__device__ __forceinline__ u64 pk2(float lo, float hi) {
    u64 d;
    asm("mov.b64 %0, {%1, %2};" : "=l"(d) : "r"(__float_as_uint(lo)), "r"(__float_as_uint(hi)));
    return d;
}
__device__ __forceinline__ void upk2(u64 v, float& lo, float& hi) {
    unsigned int a, b;
    asm("mov.b64 {%0, %1}, %2;" : "=r"(a), "=r"(b) : "l"(v));
    lo = __uint_as_float(a); hi = __uint_as_float(b);
}
__device__ __forceinline__ u64 ffma2(u64 a, u64 b, u64 c) {
    u64 d;
    asm("fma.rn.f32x2 %0, %1, %2, %3;" : "=l"(d) : "l"(a), "l"(b), "l"(c));
    return d;
}
__device__ __forceinline__ u64 fadd2(u64 a, u64 b) {
    u64 d;
    asm("add.rn.f32x2 %0, %1, %2;" : "=l"(d) : "l"(a), "l"(b));
    return d;
}
__device__ __forceinline__ float tanh_hw(float x) {
    float r; asm("tanh.approx.f32 %0, %1;" : "=f"(r) : "f"(x)); return r;
}

// ---------------- prep: embedding, weight transposes, zero cov ----------------
__global__ void __launch_bounds__(256) prep_kernel(const int* __restrict__ tgt,
                            const float* __restrict__ embed,
                            const float* __restrict__ w1,
                            const float* __restrict__ w2,
                            const float* __restrict__ w3,
                            const float* __restrict__ W_h,
                            const float* __restrict__ fc_W,
                            const float* __restrict__ W_cov) {
    int idx = blockIdx.x * 256 + threadIdx.x;
    if (idx < BB*TT*HID) {
        int bt = idx >> 8;
        g_x0[idx] = embed[tgt[bt]*HID + (idx & 255)];
    }
    if (idx < 512*256*3) {
        int o = idx / 768, rem = idx % 768, ic = rem / 3, k = rem % 3;
        int d = (k*256 + ic)*512 + o;
        g_wT1[d] = w1[idx];
        g_wT2[d] = w2[idx];
        g_wT3[d] = w3[idx];
    }
    if (idx < AA*HID) {
        int a = idx >> 8, h = idx & 255;
        g_WhT[h*AA + a] = W_h[idx];
    }
    if (idx < VV*(HID+CE)) {
        int v = idx / (HID+CE), j = idx % (HID+CE);
        g_fcWT[j*VV + v] = fc_W[idx];
    }
    if (idx < AA*26) {
        int a = idx / 26, k = idx % 26;
        float w = (k < 25) ? W_cov[a*25 + k] : 0.f;
        g_Wc2[idx] = make_float2(w, w);
    }
    if (idx < BB*HW) g_cov[idx] = 0.f;
}

// ---------------- causal GLU layer (32t x 64h tiles — R2 geometry) ----------------
__global__ void __launch_bounds__(256) glu_kernel(int src_sel, int layer,
                                                  const float* __restrict__ bias) {
    const float* xin  = src_sel ? g_x1 : g_x0;
    float*       xout = src_sel ? g_x0 : g_x1;
    const float* wT = (layer == 0) ? g_wT1 : (layer == 1) ? g_wT2 : g_wT3;

    int b  = blockIdx.x / 3;
    int t0 = (blockIdx.x % 3) * 32;
    int h0 = blockIdx.y * 64;
    __shared__ float As[34][17];
    __shared__ float Wa[3][16][64];
    __shared__ float Wg[3][16][64];
    int tid = threadIdx.x;
    int tr = (tid & 15) * 2;
    int tc = (tid >> 4) * 4;
    float aa[2][4], gg[2][4];
#pragma unroll
    for (int r = 0; r < 2; r++)
#pragma unroll
        for (int c = 0; c < 4; c++) { aa[r][c] = 0.f; gg[r][c] = 0.f; }

    for (int ic0 = 0; ic0 < 256; ic0 += 16) {
        __syncthreads();
        for (int idx = tid; idx < 34*16; idx += 256) {
            int r = idx >> 4, c = idx & 15;
            int tg = t0 - 2 + r;
            As[r][c] = (tg >= 0) ? xin[(b*TT + tg)*HID + ic0 + c] : 0.f;
        }
        for (int idx = tid; idx < 3072; idx += 256) {
            int k = idx >> 10, rem = idx & 1023, i = rem >> 6, j = rem & 63;
            const float* base = wT + (k*256 + ic0 + i)*512 + h0 + j;
            Wa[k][i][j] = base[0];
            Wg[k][i][j] = base[256];
        }
        __syncthreads();
#pragma unroll
        for (int k = 0; k < 3; k++) {
#pragma unroll
            for (int i = 0; i < 16; i++) {
                float x0 = As[tr + k][i];
                float x1 = As[tr + 1 + k][i];
#pragma unroll
                for (int c = 0; c < 4; c++) {
                    float wa = Wa[k][i][tc + c];
                    float wg = Wg[k][i][tc + c];
                    aa[0][c] = fmaf(x0, wa, aa[0][c]);
                    aa[1][c] = fmaf(x1, wa, aa[1][c]);
                    gg[0][c] = fmaf(x0, wg, gg[0][c]);
                    gg[1][c] = fmaf(x1, wg, gg[1][c]);
                }
            }
        }
    }
#pragma unroll
    for (int r = 0; r < 2; r++)
#pragma unroll
        for (int c = 0; c < 4; c++) {
            int t = t0 + tr + r, h = h0 + tc + c;
            float av = aa[r][c] + bias[h];
            float gv = gg[r][c] + bias[256 + h];
            xout[(b*TT + t)*HID + h] = av * sigmoid_fast(gv);
        }
}

// ---------------- enc_proj: EP[b,a,hw] = W_enc @ enc_feat + b_enc ----------------
__global__ void __launch_bounds__(256) encproj_kernel(const float* __restrict__ enc_feat,
                                                      const float* __restrict__ W_enc,
                                                      const float* __restrict__ b_enc) {
    int b = blockIdx.x, a0 = blockIdx.y*64, p0 = blockIdx.z*64;
    __shared__ float Ws[16][66];
    __shared__ float Fs[16][64];
    int tid = threadIdx.x;
    int ta = (tid & 15)*4, tp = (tid >> 4)*4;
    float acc[4][4];
#pragma unroll
    for (int r = 0; r < 4; r++)
#pragma unroll
        for (int c = 0; c < 4; c++) acc[r][c] = 0.f;

    for (int c0 = 0; c0 < CE; c0 += 16) {
        __syncthreads();
        for (int idx = tid; idx < 1024; idx += 256) {
            int j = idx & 15, i = idx >> 4;
            Ws[j][i] = W_enc[(a0 + i)*CE + c0 + j];
        }
        for (int idx = tid; idx < 1024; idx += 256) {
            int i = idx & 63, j = idx >> 6;
            Fs[j][i] = enc_feat[((size_t)b*CE + c0 + j)*HW + p0 + i];
        }
        __syncthreads();
#pragma unroll
        for (int j = 0; j < 16; j++) {
            float av[4], pv[4];
#pragma unroll
            for (int r = 0; r < 4; r++) av[r] = Ws[j][ta + r];
#pragma unroll
            for (int c = 0; c < 4; c++) pv[c] = Fs[j][tp + c];
#pragma unroll
            for (int r = 0; r < 4; r++)
#pragma unroll
                for (int c = 0; c < 4; c++)
                    acc[r][c] = fmaf(av[r], pv[c], acc[r][c]);
        }
    }
#pragma unroll
    for (int r = 0; r < 4; r++) {
        int a = a0 + ta + r;
        float be = b_enc[a];
#pragma unroll
        for (int c = 0; c < 4; c++)
            g_EP[((size_t)b*AA + a)*HW + p0 + tp + c] = acc[r][c] + be;
    }
}

// ---------------- q precompute ----------------
__global__ void __launch_bounds__(256) qgemm_kernel(const float* __restrict__ b_h,
                                                    const float* __restrict__ b_cov) {
    int m0 = blockIdx.x * 64;
    int n0 = blockIdx.y * 64;
    __shared__ float Hs[16][66];
    __shared__ float Ws[16][64];
    int tid = threadIdx.x;
    int tm = (tid & 15)*4, tn = (tid >> 4)*4;
    float acc[4][4];
#pragma unroll
    for (int r = 0; r < 4; r++)
#pragma unroll
        for (int c = 0; c < 4; c++) acc[r][c] = 0.f;

    for (int k0 = 0; k0 < HID; k0 += 16) {
        __syncthreads();
        for (int idx = tid; idx < 1024; idx += 256) {
            int kk = idx & 15, m = idx >> 4;
            Hs[kk][m] = g_x1[(m0 + m)*HID + k0 + kk];
        }
        for (int idx = tid; idx < 1024; idx += 256) {
            int i = idx & 63, kk = idx >> 6;
            Ws[kk][i] = g_WhT[(k0 + kk)*AA + n0 + i];
        }
        __syncthreads();
#pragma unroll
        for (int kk = 0; kk < 16; kk++) {
            float hv[4], wv[4];
#pragma unroll
            for (int r = 0; r < 4; r++) hv[r] = Hs[kk][tm + r];
#pragma unroll
            for (int c = 0; c < 4; c++) wv[c] = Ws[kk][tn + c];
#pragma unroll
            for (int r = 0; r < 4; r++)
#pragma unroll
                for (int c = 0; c < 4; c++)
                    acc[r][c] = fmaf(hv[r], wv[c], acc[r][c]);
        }
    }
#pragma unroll
    for (int r = 0; r < 4; r++)
#pragma unroll
        for (int c = 0; c < 4; c++) {
            int n = n0 + tn + c;
            g_QB[(m0 + tm + r)*AA + n] = acc[r][c] + b_h[n] + b_cov[n];
        }
}

// ---------------- per-step energy (f32x2-packed, a-chunked, prefetch-2) ----------------
__global__ void __launch_bounds__(128) energy_kernel(const float* __restrict__ v_attn, int t) {
    int b     = blockIdx.x;
    int strip = blockIdx.y;
    int zc    = blockIdx.z;
    int a0    = zc * ACH;
    __shared__ float sCov[12][68];
    __shared__ __align__(16) float2 sW[ACH*26];
    __shared__ float2 sQ2[ACH];
    __shared__ float2 sV2[ACH];
    int tid = threadIdx.x;
    int r0 = strip * 8;

    for (int idx = tid; idx < 12*68; idx += 128) {
        int rr = idx / 68, cc = idx % 68;
        int h = r0 - 2 + rr, w = cc - 2;
        sCov[rr][cc] = (h >= 0 && h < HH_ && (unsigned)w < WW_)
                       ? g_cov[b*HW + h*WW_ + w] : 0.f;
    }
    for (int idx = tid; idx < ACH*26; idx += 128)
        sW[idx] = g_Wc2[a0*26 + idx];
    if (tid < ACH) {
        float q = g_QB[(b*TT + t)*AA + a0 + tid];
        sQ2[tid] = make_float2(q, q);
        float v = v_attn[a0 + tid];
        sV2[tid] = make_float2(v, v);
    }
    __syncthreads();

    int row = tid >> 4;
    int c0  = (tid & 15) * 4;

    u64 pp[5][7];
#pragma unroll
    for (int dy = 0; dy < 5; dy++)
#pragma unroll
        for (int dx = 0; dx < 7; dx++)
            pp[dy][dx] = pk2(sCov[row + dy][c0 + dx], sCov[row + dy][c0 + dx + 1]);

    int pix = (r0 + row)*WW_ + c0;
    const int STR = HW/4;                               // 256 ulonglong2 per a-row
    const ulonglong2* ep2 = (const ulonglong2*)(g_EP + ((size_t)b*AA + a0)*HW + pix);
    const ulonglong2* wb  = (const ulonglong2*)sW;

    u64 e0 = 0ull, e1 = 0ull;
    ulonglong2 buf0 = ep2[0];
    ulonglong2 buf1 = ep2[STR];
    ep2 += 2*STR;

#pragma unroll 1
    for (int aa = 0; aa < ACH; aa++) {
        ulonglong2 cur = buf0;
        buf0 = buf1;
        if (aa < ACH - 2) { buf1 = *ep2; ep2 += STR; }

        const ulonglong2* w2 = wb + aa*13;
        u64 a00 = 0ull, a01 = 0ull, a10 = 0ull, a11 = 0ull;
#pragma unroll
        for (int j = 0; j < 13; j++) {
            ulonglong2 w = w2[j];
            {   const int k = 2*j;
                if (k < 25) {
                    const int dy = k / 5, dx = k % 5;
                    a00 = ffma2(pp[dy][dx],     w.x, a00);
                    a10 = ffma2(pp[dy][dx + 2], w.x, a10);
                }
            }
            {   const int k = 2*j + 1;
                if (k < 25) {
                    const int dy = k / 5, dx = k % 5;
                    a01 = ffma2(pp[dy][dx],     w.y, a01);
                    a11 = ffma2(pp[dy][dx + 2], w.y, a11);
                }
            }
        }
        u64 q2 = *(const u64*)&sQ2[aa];
        u64 g0 = fadd2(fadd2(a00, a01), fadd2(cur.x, q2));
        u64 g1 = fadd2(fadd2(a10, a11), fadd2(cur.y, q2));
        float s0, s1, s2, s3;
        upk2(g0, s0, s1); upk2(g1, s2, s3);
        float t0 = tanh_hw(s0), t1 = tanh_hw(s1);
        float t2 = tanh_hw(s2), t3 = tanh_hw(s3);
        u64 v2 = *(const u64*)&sV2[aa];
        e0 = ffma2(pk2(t0, t1), v2, e0);
        e1 = ffma2(pk2(t2, t3), v2, e1);
    }
    float r0_, r1_, r2_, r3_;
    upk2(e0, r0_, r1_); upk2(e1, r2_, r3_);
    *(float4*)&g_epart[(zc*BB + b)*HW + pix] = make_float4(r0_, r1_, r2_, r3_);
}

// ---------------- per-step softmax + cov update + alpha store ----------------
__global__ void __launch_bounds__(256) softcov_kernel(int t) {
    int b = blockIdx.x;
    __shared__ float redm[8];
    __shared__ float reds[8];
    int tid = threadIdx.x, lane = tid & 31, warp = tid >> 5;

    float4 ev = make_float4(0.f, 0.f, 0.f, 0.f);
#pragma unroll
    for (int z = 0; z < NZ; z++) {
        float4 p = ((const float4*)(g_epart + (z*BB + b)*HW))[tid];
        ev.x += p.x; ev.y += p.y; ev.z += p.z; ev.w += p.w;
    }
    float m = fmaxf(fmaxf(ev.x, ev.y), fmaxf(ev.z, ev.w));
#pragma unroll
    for (int o = 16; o; o >>= 1) m = fmaxf(m, __shfl_xor_sync(~0u, m, o));
    if (lane == 0) redm[warp] = m;
    __syncthreads();
    m = redm[0];
#pragma unroll
    for (int i = 1; i < 8; i++) m = fmaxf(m, redm[i]);

    float4 exv;
    exv.x = __expf(ev.x - m); exv.y = __expf(ev.y - m);
    exv.z = __expf(ev.z - m); exv.w = __expf(ev.w - m);
    float s = exv.x + exv.y + exv.z + exv.w;
#pragma unroll
    for (int o = 16; o; o >>= 1) s += __shfl_xor_sync(~0u, s, o);
    if (lane == 0) reds[warp] = s;
    __syncthreads();
    s = reds[0];
#pragma unroll
    for (int i = 1; i < 8; i++) s += reds[i];
    float inv = __fdividef(1.f, s);

    float4 al;
    al.x = exv.x*inv; al.y = exv.y*inv; al.z = exv.z*inv; al.w = exv.w*inv;
    ((float4*)(g_alpha + ((size_t)b*TT + t)*HW))[tid] = al;

    float4* cv = (float4*)(g_cov + b*HW);
    float4 c = cv[tid];
    c.x += al.x; c.y += al.y; c.z += al.z; c.w += al.w;
    cv[tid] = c;
}

// ---------------- batched ctx GEMM: ctx[b,t,c] = sum_px alpha[b,t,px]*enc_feat[b,c,px] ----------------
__global__ void __launch_bounds__(256) ctxgemm_kernel(const float* __restrict__ enc_feat) {
    int b  = blockIdx.x;
    int m0 = blockIdx.y * 64;   // t tile (96 -> 2 tiles)
    int n0 = blockIdx.z * 64;   // c tile (400 -> 7 tiles)
    __shared__ float As[16][66];
    __shared__ float Fs[16][64];
    int tid = threadIdx.x;
    int tm = (tid & 15)*4, tn = (tid >> 4)*4;
    float acc[4][4];
#pragma unroll
    for (int r = 0; r < 4; r++)
#pragma unroll
        for (int c = 0; c < 4; c++) acc[r][c] = 0.f;

    for (int k0 = 0; k0 < HW; k0 += 16) {
        __syncthreads();
        for (int idx = tid; idx < 1024; idx += 256) {
            int kk = idx & 15, mm = idx >> 4;
            int tt = m0 + mm;
            As[kk][mm] = (tt < TT) ? g_alpha[((size_t)b*TT + tt)*HW + k0 + kk] : 0.f;
        }
        for (int idx = tid; idx < 1024; idx += 256) {
            int i = idx & 63, kk = idx >> 6;
            int cc = n0 + i;
            Fs[kk][i] = (cc < CE) ? enc_feat[((size_t)b*CE + cc)*HW + k0 + kk] : 0.f;
        }
        __syncthreads();
#pragma unroll
        for (int kk = 0; kk < 16; kk++) {
            float av[4], fv[4];
#pragma unroll
            for (int r = 0; r < 4; r++) av[r] = As[kk][tm + r];
#pragma unroll
            for (int c = 0; c < 4; c++) fv[c] = Fs[kk][tn + c];
#pragma unroll
            for (int r = 0; r < 4; r++)
#pragma unroll
                for (int c = 0; c < 4; c++)
                    acc[r][c] = fmaf(av[r], fv[c], acc[r][c]);
        }
    }
#pragma unroll
    for (int r = 0; r < 4; r++) {
        int tt = m0 + tm + r;
        if (tt < TT) {
#pragma unroll
            for (int c = 0; c < 4; c++) {
                int cc = n0 + tn + c;
                if (cc < CE) g_ctxall[((size_t)b*TT + tt)*CE + cc] = acc[r][c];
            }
        }
    }
}

// ---------------- final fc ----------------
__global__ void __launch_bounds__(256) fc_kernel(const float* __restrict__ fc_b,
                                                 float* __restrict__ out) {
    int m0 = blockIdx.x * 64;
    int n0 = blockIdx.y * 64;
    __shared__ float Is[16][66];
    __shared__ float Ws[16][64];
    int tid = threadIdx.x;
    int tm = (tid & 15)*4, tn = (tid >> 4)*4;
    float acc[4][4];
#pragma unroll
    for (int r = 0; r < 4; r++)
#pragma unroll
        for (int c = 0; c < 4; c++) acc[r][c] = 0.f;

    for (int k0 = 0; k0 < HID + CE; k0 += 16) {
        __syncthreads();
        const float* src; int stride, off;
        if (k0 < HID) { src = g_x1;     stride = HID; off = k0; }
        else          { src = g_ctxall; stride = CE;  off = k0 - HID; }
        for (int idx = tid; idx < 1024; idx += 256) {
            int kk = idx & 15, mm = idx >> 4;
            Is[kk][mm] = src[(m0 + mm)*stride + off + kk];
        }
        for (int idx = tid; idx < 1024; idx += 256) {
            int i = idx & 63, kk = idx >> 6;
            Ws[kk][i] = g_fcWT[(k0 + kk)*VV + n0 + i];
        }
        __syncthreads();
#pragma unroll
        for (int kk = 0; kk < 16; kk++) {
            float iv[4], wv[4];
#pragma unroll
            for (int r = 0; r < 4; r++) iv[r] = Is[kk][tm + r];
#pragma unroll
            for (int c = 0; c < 4; c++) wv[c] = Ws[kk][tn + c];
#pragma unroll
            for (int r = 0; r < 4; r++)
#pragma unroll
                for (int c = 0; c < 4; c++)
                    acc[r][c] = fmaf(iv[r], wv[c], acc[r][c]);
        }
    }
#pragma unroll
    for (int r = 0; r < 4; r++)
#pragma unroll
        for (int c = 0; c < 4; c++) {
            int n = n0 + tn + c;
            out[(m0 + tm + r)*VV + n] = acc[r][c] + fc_b[n];
        }
}

// ---------------- launch ----------------
extern "C" void kernel_launch(void* const* d_in, const int* in_sizes, int n_in,
                              void* d_out, int out_size) {
    const float* enc_feat = (const float*)d_in[0];
    const int*   tgt      = (const int*)  d_in[1];
    const float* embed    = (const float*)d_in[2];
    const float* w1       = (const float*)d_in[3];
    const float* b1       = (const float*)d_in[4];
    const float* w2       = (const float*)d_in[5];
    const float* b2       = (const float*)d_in[6];
    const float* w3       = (const float*)d_in[7];
    const float* b3       = (const float*)d_in[8];
    const float* W_enc    = (const float*)d_in[9];
    const float* b_enc    = (const float*)d_in[10];
    const float* W_h      = (const float*)d_in[11];
    const float* b_h      = (const float*)d_in[12];
    const float* W_cov    = (const float*)d_in[13];
    const float* b_cov    = (const float*)d_in[14];
    const float* v_attn   = (const float*)d_in[15];
    const float* fc_W     = (const float*)d_in[16];
    const float* fc_b     = (const float*)d_in[17];
    float* out = (float*)d_out;

    prep_kernel<<<3072, 256>>>(tgt, embed, w1, w2, w3, W_h, fc_W, W_cov);

    dim3 gglu(BB*3, 4);
    glu_kernel<<<gglu, 256>>>(0, 0, b1);   // g_x0 -> g_x1
    glu_kernel<<<gglu, 256>>>(1, 1, b2);   // g_x1 -> g_x0
    glu_kernel<<<gglu, 256>>>(0, 2, b3);   // g_x0 -> g_x1 (= hidd)

    encproj_kernel<<<dim3(BB, 4, 16), 256>>>(enc_feat, W_enc, b_enc);
    qgemm_kernel<<<dim3(48, 4), 256>>>(b_h, b_cov);

    for (int t = 0; t < TT; t++) {
        energy_kernel<<<dim3(BB, 2, NZ), 128>>>(v_attn, t);
        softcov_kernel<<<BB, 256>>>(t);
    }

    ctxgemm_kernel<<<dim3(BB, 2, 7), 256>>>(enc_feat);
    fc_kernel<<<dim3(48, 4), 256>>>(fc_b, out);
}